// round 15
// baseline (speedup 1.0000x reference)
#include <cuda_runtime.h>
#include <cuda_fp16.h>
#include <math.h>

#define NRES 384
#define NNPIX (NRES*NRES)          // 147456
#define CH 128
#define NH 4
#define KD 32
#define QSCALE 0.17677669529663689f  // 1/sqrt(32)
#define LOG2E 1.4426950408889634f

#define PADA2 68   // X half2 pad (words/row). rows offset 4 banks -> LDSM conflict-free
#define PADW  68   // W^T half2 pad (words/row), same property
#define PADK2 392  // K half2 pad: B-frag bank = 8*gc+gr -> conflict-free
#define PADH 196   // V half2 pad (key pairs): bank = 4*gr+gc -> conflict-free

// ---------------- scratch (fp16 intermediates) --------------------------------
__device__ __align__(16) __half  g_nb [(size_t)NH*NNPIX];
__device__ __align__(16) __half  g_q  [(size_t)NNPIX*CH];
__device__ __align__(16) __half  g_k  [(size_t)NNPIX*CH];
__device__ __align__(16) __half  g_v  [(size_t)NNPIX*CH];
__device__ __align__(16) __half  g_g  [(size_t)NNPIX*CH];
__device__ __align__(16) __half  g_att[(size_t)NNPIX*CH];
__device__ __align__(16) unsigned g_wt[5*128*64];   // 5 weight mats TRANSPOSED [n][k2] half2

// ---------------- helpers -----------------------------------------------------
__device__ __forceinline__ unsigned h2pack(float lo, float hi) {
    unsigned u;
    asm("cvt.rn.f16x2.f32 %0, %1, %2;" : "=r"(u) : "f"(hi), "f"(lo));
    return u;
}
__device__ __forceinline__ float2 h2unpack(unsigned u) {
    __half2 h = *(__half2*)&u;
    return __half22float2(h);
}
__device__ __forceinline__ float ex2(float x) {
    float y;
    asm("ex2.approx.ftz.f32 %0, %1;" : "=f"(y) : "f"(x));
    return y;
}
__device__ __forceinline__ void mma_f16(float c[4], const unsigned a[4], unsigned b0, unsigned b1) {
    asm volatile(
        "mma.sync.aligned.m16n8k16.row.col.f32.f16.f16.f32 "
        "{%0,%1,%2,%3}, {%4,%5,%6,%7}, {%8,%9}, {%0,%1,%2,%3};"
        : "+f"(c[0]), "+f"(c[1]), "+f"(c[2]), "+f"(c[3])
        : "r"(a[0]), "r"(a[1]), "r"(a[2]), "r"(a[3]), "r"(b0), "r"(b1));
}
__device__ __forceinline__ void ldsm_x4(unsigned r[4], unsigned addr) {
    asm volatile("ldmatrix.sync.aligned.m8n8.x4.shared.b16 {%0,%1,%2,%3}, [%4];"
        : "=r"(r[0]), "=r"(r[1]), "=r"(r[2]), "=r"(r[3]) : "r"(addr));
}
__device__ __forceinline__ unsigned smem_u32(const void* p) {
    return (unsigned)__cvta_generic_to_shared(p);
}
__device__ __forceinline__ void cp16(unsigned dst_sh, const void* src) {
    asm volatile("cp.async.cg.shared.global [%0], [%1], 16;" :: "r"(dst_sh), "l"(src));
}
__device__ __forceinline__ void cp_commit() {
    asm volatile("cp.async.commit_group;");
}
__device__ __forceinline__ void cp_wait0() {
    asm volatile("cp.async.wait_group 0;" ::: "memory");
}

// ---------------- kernel 0: pack weights transposed [n][k2] half2 -------------
__global__ __launch_bounds__(256) void wpack_kernel(
    const float* __restrict__ qw, const float* __restrict__ kw,
    const float* __restrict__ vw, const float* __restrict__ gw,
    const float* __restrict__ ow)
{
    const int i = blockIdx.x * 256 + threadIdx.x;     // [0, 5*8192)
    const int m = i >> 13;
    const int r = i & 8191;
    const int n = r >> 6, k2 = r & 63;
    const float* W = (m==0) ? qw : (m==1) ? kw : (m==2) ? vw : (m==3) ? gw : ow;
    g_wt[i] = h2pack(W[(2*k2)*CH + n], W[(2*k2+1)*CH + n]);
}

// ---------------- kernel 1: fused LN + nb-bias + q/k/v/gate (fp16 mma) -------
__global__ __launch_bounds__(256, 4) void lnproj_mma_kernel(
    const float* __restrict__ pact, const float* __restrict__ lns,
    const float* __restrict__ lnb, const float* __restrict__ f2w,
    const float* __restrict__ gb)
{
    extern __shared__ unsigned smu[];
    unsigned* xs  = smu;               // [64 rows][PADA2] half2 (k-pairs)
    unsigned* wst = smu + 64*PADA2;    // [128 n][PADW] half2 (k-pairs), transposed W
    const int tid = threadIdx.x;
    const int warp = tid >> 5, lane = tid & 31;
    const int gr = lane >> 2, gc = lane & 3;
    const int mw = warp & 1, nw = warp >> 1;
    const int rw0 = mw * 32, nw0 = nw * 32;
    const int r0 = blockIdx.x * 64;

    const unsigned xs_sh  = smem_u32(xs);
    const unsigned wst_sh = smem_u32(wst);
    const int lrow = lane & 15, lchunk = (lane >> 4) * 16;
    const unsigned aAddr0 = xs_sh  + (rw0      + lrow)*PADA2*4 + lchunk;
    const unsigned aAddr1 = xs_sh  + (rw0 + 16 + lrow)*PADA2*4 + lchunk;
    const unsigned bAddr0 = wst_sh + (nw0      + lrow)*PADW*4  + lchunk;
    const unsigned bAddr1 = wst_sh + (nw0 + 16 + lrow)*PADW*4  + lchunk;

    // ---- prefetch W[0] via cp.async: hidden behind the whole LN stage -------
    for (int i = tid; i < 128*16; i += 256) {
        const int n = i >> 4, c4 = i & 15;
        cp16(wst_sh + (n*PADW + c4*4)*4, g_wt + n*64 + c4*4);
    }
    cp_commit();

    // ---- stage 1: LayerNorm (single-pass sum/sumsq) + nb bias ---------------
    {
        const float4 sc = ((const float4*)lns)[lane];
        const float4 bi = ((const float4*)lnb)[lane];
        const float4* w4 = (const float4*)f2w;
        const float4 w0 = w4[lane*4+0], w1 = w4[lane*4+1],
                     w2 = w4[lane*4+2], w3 = w4[lane*4+3];
        #pragma unroll 4
        for (int k = 0; k < 8; ++k) {
            const int r = k*8 + warp;
            const size_t p = (size_t)(r0 + r);
            float4 v = ((const float4*)(pact + p*CH))[lane];
            float s  = v.x + v.y + v.z + v.w;
            float ss = v.x*v.x + v.y*v.y + v.z*v.z + v.w*v.w;
            #pragma unroll
            for (int o = 16; o; o >>= 1) {
                s  += __shfl_xor_sync(0xffffffffu, s,  o);
                ss += __shfl_xor_sync(0xffffffffu, ss, o);
            }
            const float mu  = s * (1.0f/CH);
            const float var = ss * (1.0f/CH) - mu*mu;
            const float inv = rsqrtf(var + 1e-5f);
            float4 xn;
            xn.x = (v.x-mu)*inv*sc.x + bi.x;
            xn.y = (v.y-mu)*inv*sc.y + bi.y;
            xn.z = (v.z-mu)*inv*sc.z + bi.z;
            xn.w = (v.w-mu)*inv*sc.w + bi.w;
            *(uint2*)(xs + r*PADA2 + lane*2) =
                make_uint2(h2pack(xn.x, xn.y), h2pack(xn.z, xn.w));

            float n0 = xn.x*w0.x + xn.y*w1.x + xn.z*w2.x + xn.w*w3.x;
            float n1 = xn.x*w0.y + xn.y*w1.y + xn.z*w2.y + xn.w*w3.y;
            float n2 = xn.x*w0.z + xn.y*w1.z + xn.z*w2.z + xn.w*w3.z;
            float n3 = xn.x*w0.w + xn.y*w1.w + xn.z*w2.w + xn.w*w3.w;
            #pragma unroll
            for (int o = 16; o; o >>= 1) {
                n0 += __shfl_xor_sync(0xffffffffu, n0, o);
                n1 += __shfl_xor_sync(0xffffffffu, n1, o);
                n2 += __shfl_xor_sync(0xffffffffu, n2, o);
                n3 += __shfl_xor_sync(0xffffffffu, n3, o);
            }
            if (lane == 0) {     // nb scaled by log2e for exp2-based softmax
                g_nb[0*(size_t)NNPIX + p] = __float2half(n0*LOG2E);
                g_nb[1*(size_t)NNPIX + p] = __float2half(n1*LOG2E);
                g_nb[2*(size_t)NNPIX + p] = __float2half(n2*LOG2E);
                g_nb[3*(size_t)NNPIX + p] = __float2half(n3*LOG2E);
            }
        }
    }

    // ---- stage 2: four W passes, cp.async pipelined --------------------------
    for (int m = 0; m < 4; ++m) {
        cp_wait0();
        __syncthreads();          // W[m] staged + (m==0) xs visible

        float c[2][4][4];
        #pragma unroll
        for (int mi = 0; mi < 2; ++mi)
            #pragma unroll
            for (int ni = 0; ni < 4; ++ni)
                #pragma unroll
                for (int t = 0; t < 4; ++t) c[mi][ni][t] = 0.f;

        #pragma unroll
        for (int t = 0; t < 8; ++t) {
            const unsigned koff = t * 32;
            unsigned a[2][4], bf[2][4];
            ldsm_x4(a[0], aAddr0 + koff);
            ldsm_x4(a[1], aAddr1 + koff);
            ldsm_x4(bf[0], bAddr0 + koff);
            ldsm_x4(bf[1], bAddr1 + koff);
            #pragma unroll
            for (int mi = 0; mi < 2; ++mi)
                #pragma unroll
                for (int ni = 0; ni < 4; ++ni)
                    mma_f16(c[mi][ni], a[mi], bf[ni>>1][ni&1], bf[ni>>1][2+(ni&1)]);
        }

        __syncthreads();          // everyone done reading W[m]
        if (m < 3) {              // launch W[m+1] load; overlaps epilogue
            const unsigned* Wt = g_wt + (m+1)*8192;
            for (int i = tid; i < 128*16; i += 256) {
                const int n = i >> 4, c4 = i & 15;
                cp16(wst_sh + (n*PADW + c4*4)*4, Wt + n*64 + c4*4);
            }
            cp_commit();
        }

        __half* outp = (m==0) ? g_q : (m==1) ? g_k : (m==2) ? g_v : g_g;
        #pragma unroll
        for (int mi = 0; mi < 2; ++mi) {
            const int row0 = r0 + rw0 + mi*16 + gr;
            #pragma unroll
            for (int ni = 0; ni < 4; ++ni) {
                const int col = nw0 + ni*8 + gc*2;
                float v0x = c[mi][ni][0], v0y = c[mi][ni][1];
                float v1x = c[mi][ni][2], v1y = c[mi][ni][3];
                if (m == 0) {
                    const float qs = QSCALE * LOG2E;
                    v0x*=qs; v0y*=qs; v1x*=qs; v1y*=qs;
                }
                if (m == 3) {
                    const float2 bb = *(const float2*)(gb + col);
                    v0x = 1.f/(1.f + __expf(-(v0x + bb.x)));
                    v0y = 1.f/(1.f + __expf(-(v0y + bb.y)));
                    v1x = 1.f/(1.f + __expf(-(v1x + bb.x)));
                    v1y = 1.f/(1.f + __expf(-(v1y + bb.y)));
                }
                *(unsigned*)(outp + (size_t)row0*CH + col)     = h2pack(v0x, v0y);
                *(unsigned*)(outp + (size_t)(row0+8)*CH + col) = h2pack(v1x, v1y);
            }
        }
    }
}

// ---------------- kernel 2: flash attention, fp16 mma, exp2 softmax ----------
// s accumulators initialized with bias (loads overlap QK mma);
// exp/pack/PV interleaved per 16-key group.
__global__ __launch_bounds__(256, 3) void attn_mma_kernel(const float* __restrict__ mask)
{
    extern __shared__ unsigned sm_u[];
    unsigned* Kd2 = sm_u;                      // [16 d-pairs][PADK2] half2
    unsigned* Vs  = Kd2 + 16*PADK2;            // [32 d][PADH] half2 (key-pairs)
    float* mrow   = (float*)(Vs + 32*PADH);    // [384]
    const int b = blockIdx.x, h = blockIdx.y;
    const int tid = threadIdx.x, warp = tid >> 5, lane = tid & 31;
    const int gr = lane >> 2, gc = lane & 3;

    for (int i = tid; i < 384*4; i += 256) {
        const int key = i >> 2, q4 = i & 3;
        const unsigned* kb = (const unsigned*)(g_k + ((size_t)(b*NRES)+key)*CH + h*KD);
        uint4 kv = ((const uint4*)kb)[q4];
        Kd2[(q4*4+0)*PADK2 + key] = kv.x;
        Kd2[(q4*4+1)*PADK2 + key] = kv.y;
        Kd2[(q4*4+2)*PADK2 + key] = kv.z;
        Kd2[(q4*4+3)*PADK2 + key] = kv.w;
    }
    for (int i = tid; i < 192*8; i += 256) {
        const int kp = i >> 3, c4 = i & 7;
        const unsigned* v0 = (const unsigned*)(g_v + ((size_t)(b*NRES)+2*kp)*CH + h*KD);
        const unsigned* v1 = (const unsigned*)(g_v + ((size_t)(b*NRES)+2*kp+1)*CH + h*KD);
        uint2 a  = ((const uint2*)v0)[c4];
        uint2 bb = ((const uint2*)v1)[c4];
        Vs[(4*c4+0)*PADH + kp] = __byte_perm(a.x, bb.x, 0x5410);
        Vs[(4*c4+1)*PADH + kp] = __byte_perm(a.x, bb.x, 0x7632);
        Vs[(4*c4+2)*PADH + kp] = __byte_perm(a.y, bb.y, 0x5410);
        Vs[(4*c4+3)*PADH + kp] = __byte_perm(a.y, bb.y, 0x7632);
    }
    for (int i = tid; i < NRES; i += 256)
        mrow[i] = (1e9f*LOG2E) * (mask[(size_t)b*NRES + i] - 1.f);
    __syncthreads();

    for (int p = 0; p < 3; ++p) {
        const int q0 = p*128 + warp*16;
        unsigned qa[2][4];
        const unsigned* qlo = (const unsigned*)(g_q + ((size_t)(b*NRES)+q0+gr)*CH + h*KD);
        const unsigned* qhi = (const unsigned*)(g_q + ((size_t)(b*NRES)+q0+gr+8)*CH + h*KD);
        #pragma unroll
        for (int kc = 0; kc < 2; ++kc) {
            qa[kc][0] = qlo[kc*8 + gc];
            qa[kc][1] = qhi[kc*8 + gc];
            qa[kc][2] = qlo[kc*8 + gc + 4];
            qa[kc][3] = qhi[kc*8 + gc + 4];
        }
        const __half* nb0 = g_nb + (size_t)h*NNPIX + (size_t)(q0+gr)*NRES;
        const __half* nb1 = nb0 + (size_t)8*NRES;

        float sum0 = 0.f, sum1 = 0.f;
        float O[4][4];
        #pragma unroll
        for (int vt = 0; vt < 4; ++vt)
            #pragma unroll
            for (int t = 0; t < 4; ++t) O[vt][t] = 0.f;

        for (int c = 0; c < 6; ++c) {
            const int c0 = c*64;
            float s[8][4];
            // init score accumulators with bias; QK mma accumulates on top.
            // loads issue first and overlap the mma block below.
            #pragma unroll
            for (int t = 0; t < 8; ++t) {
                const int col = c0 + t*8 + gc*2;
                const float2 mr  = *(const float2*)(mrow + col);
                const float2 nlo = h2unpack(*(const unsigned*)(nb0 + col));
                const float2 nhi = h2unpack(*(const unsigned*)(nb1 + col));
                s[t][0] = mr.x + nlo.x;
                s[t][1] = mr.y + nlo.y;
                s[t][2] = mr.x + nhi.x;
                s[t][3] = mr.y + nhi.y;
            }
            #pragma unroll
            for (int t = 0; t < 8; ++t) {
                const int n0 = c0 + t*8 + gr;
                #pragma unroll
                for (int kc = 0; kc < 2; ++kc) {
                    mma_f16(s[t], qa[kc],
                            Kd2[(kc*8+gc  )*PADK2 + n0],
                            Kd2[(kc*8+gc+4)*PADK2 + n0]);
                }
            }
            // interleaved exp + pack + PV per 16-key group (short dep path)
            #pragma unroll
            for (int kc16 = 0; kc16 < 4; ++kc16) {
                const int e = 2*kc16, o = e+1;
                s[e][0] = ex2(s[e][0]); s[e][1] = ex2(s[e][1]);
                s[e][2] = ex2(s[e][2]); s[e][3] = ex2(s[e][3]);
                s[o][0] = ex2(s[o][0]); s[o][1] = ex2(s[o][1]);
                s[o][2] = ex2(s[o][2]); s[o][3] = ex2(s[o][3]);
                sum0 += s[e][0] + s[e][1] + s[o][0] + s[o][1];
                sum1 += s[e][2] + s[e][3] + s[o][2] + s[o][3];
                unsigned pa[4];
                pa[0] = h2pack(s[e][0], s[e][1]);
                pa[1] = h2pack(s[e][2], s[e][3]);
                pa[2] = h2pack(s[o][0], s[o][1]);
                pa[3] = h2pack(s[o][2], s[o][3]);
                const int kpb = (c0 >> 1) + kc16*8;
                #pragma unroll
                for (int vt = 0; vt < 4; ++vt) {
                    const unsigned* vrow = Vs + (vt*8+gr)*PADH + kpb;
                    mma_f16(O[vt], pa, vrow[gc], vrow[gc+4]);
                }
            }
        }

        sum0 += __shfl_xor_sync(0xffffffffu, sum0, 1);
        sum0 += __shfl_xor_sync(0xffffffffu, sum0, 2);
        sum1 += __shfl_xor_sync(0xffffffffu, sum1, 1);
        sum1 += __shfl_xor_sync(0xffffffffu, sum1, 2);
        const float inv0 = 1.f / sum0, inv1 = 1.f / sum1;

        const size_t orow0 = ((size_t)(b*NRES)+q0+gr)*CH + h*KD;
        const size_t orow1 = orow0 + (size_t)8*CH;
        #pragma unroll
        for (int vt = 0; vt < 4; ++vt) {
            const int cl = vt*8 + gc*2;
            const float2 g0 = h2unpack(*(const unsigned*)(g_g + orow0 + cl));
            const float2 g1 = h2unpack(*(const unsigned*)(g_g + orow1 + cl));
            *(unsigned*)(g_att + orow0 + cl) =
                h2pack(O[vt][0]*inv0*g0.x, O[vt][1]*inv0*g0.y);
            *(unsigned*)(g_att + orow1 + cl) =
                h2pack(O[vt][2]*inv1*g1.x, O[vt][3]*inv1*g1.y);
        }
    }
}

// ---------------- kernel 3: output projection (fp16 mma + ldmatrix) ----------
__global__ __launch_bounds__(256, 4) void out_mma_kernel(
    const float* __restrict__ ob, float* __restrict__ out)
{
    extern __shared__ unsigned smu[];
    unsigned* xs  = smu;               // [64][PADA2]
    unsigned* wst = smu + 64*PADA2;    // [128][PADW] transposed W
    const int tid = threadIdx.x;
    const int warp = tid >> 5, lane = tid & 31;
    const int gr = lane >> 2, gc = lane & 3;
    const int mw = warp & 1, nw = warp >> 1;
    const int rw0 = mw * 32, nw0 = nw * 32;
    const int r0 = blockIdx.x * 64;

    const unsigned xs_sh  = smem_u32(xs);
    const unsigned wst_sh = smem_u32(wst);
    const int lrow = lane & 15, lchunk = (lane >> 4) * 16;
    const unsigned aAddr0 = xs_sh  + (rw0      + lrow)*PADA2*4 + lchunk;
    const unsigned aAddr1 = xs_sh  + (rw0 + 16 + lrow)*PADA2*4 + lchunk;
    const unsigned bAddr0 = wst_sh + (nw0      + lrow)*PADW*4  + lchunk;
    const unsigned bAddr1 = wst_sh + (nw0 + 16 + lrow)*PADW*4  + lchunk;

    // X + W staging via cp.async (issue everything, wait once)
    for (int i = tid; i < 64*16; i += 256) {
        const int r = i >> 4, c4 = i & 15;
        cp16(xs_sh + (r*PADA2 + c4*4)*4,
             (const char*)(g_att + (size_t)(r0 + r)*CH) + c4*16);
    }
    {
        const unsigned* Wt = g_wt + 4*8192;
        for (int i = tid; i < 128*16; i += 256) {
            const int n = i >> 4, c4 = i & 15;
            cp16(wst_sh + (n*PADW + c4*4)*4, Wt + n*64 + c4*4);
        }
    }
    cp_commit();
    cp_wait0();
    __syncthreads();

    float c[2][4][4];
    #pragma unroll
    for (int mi = 0; mi < 2; ++mi)
        #pragma unroll
        for (int ni = 0; ni < 4; ++ni)
            #pragma unroll
            for (int t = 0; t < 4; ++t) c[mi][ni][t] = 0.f;

    #pragma unroll
    for (int t = 0; t < 8; ++t) {
        const unsigned koff = t * 32;
        unsigned a[2][4], bf[2][4];
        ldsm_x4(a[0], aAddr0 + koff);
        ldsm_x4(a[1], aAddr1 + koff);
        ldsm_x4(bf[0], bAddr0 + koff);
        ldsm_x4(bf[1], bAddr1 + koff);
        #pragma unroll
        for (int mi = 0; mi < 2; ++mi)
            #pragma unroll
            for (int ni = 0; ni < 4; ++ni)
                mma_f16(c[mi][ni], a[mi], bf[ni>>1][ni&1], bf[ni>>1][2+(ni&1)]);
    }

    #pragma unroll
    for (int mi = 0; mi < 2; ++mi) {
        const int row0 = r0 + rw0 + mi*16 + gr;
        #pragma unroll
        for (int ni = 0; ni < 4; ++ni) {
            const int col = nw0 + ni*8 + gc*2;
            const float2 bb = *(const float2*)(ob + col);
            *(float2*)(out + (size_t)row0*CH + col) =
                make_float2(c[mi][ni][0] + bb.x, c[mi][ni][1] + bb.y);
            *(float2*)(out + (size_t)(row0+8)*CH + col) =
                make_float2(c[mi][ni][2] + bb.x, c[mi][ni][3] + bb.y);
        }
    }
}

// ---------------- launcher ---------------------------------------------------
extern "C" void kernel_launch(void* const* d_in, const int* in_sizes, int n_in,
                              void* d_out, int out_size)
{
    const float* pact = (const float*)d_in[0];
    const float* mask = (const float*)d_in[1];
    const float* lns  = (const float*)d_in[2];
    const float* lnb  = (const float*)d_in[3];
    const float* f2w  = (const float*)d_in[4];
    const float* qw   = (const float*)d_in[5];
    const float* kw   = (const float*)d_in[6];
    const float* vw   = (const float*)d_in[7];
    const float* gw   = (const float*)d_in[8];
    const float* gb   = (const float*)d_in[9];
    const float* ow   = (const float*)d_in[10];
    const float* ob   = (const float*)d_in[11];
    float* out = (float*)d_out;

    const int GEMM_SMEM = (64*PADA2 + 128*PADW) * 4;              // 52224
    const int ATTN_SMEM = (16*PADK2 + 32*PADH + NRES) * 4;        // 51712

    cudaFuncSetAttribute(lnproj_mma_kernel, cudaFuncAttributeMaxDynamicSharedMemorySize, GEMM_SMEM);
    cudaFuncSetAttribute(out_mma_kernel,    cudaFuncAttributeMaxDynamicSharedMemorySize, GEMM_SMEM);
    cudaFuncSetAttribute(attn_mma_kernel,   cudaFuncAttributeMaxDynamicSharedMemorySize, ATTN_SMEM);

    wpack_kernel<<<160, 256>>>(qw, kw, vw, gw, ow);
    lnproj_mma_kernel<<<NNPIX/64, 256, GEMM_SMEM>>>(pact, lns, lnb, f2w, gb);
    attn_mma_kernel<<<dim3(NRES, NH), 256, ATTN_SMEM>>>(mask);
    out_mma_kernel<<<NNPIX/64, 256, GEMM_SMEM>>>(ob, out);
}